// round 3
// baseline (speedup 1.0000x reference)
#include <cuda_runtime.h>

// Fully fused FCBlock network, fp32, FFMA2 (fma.rn.f32x2) compute.
//
// N=65536 rows, H=512, L=3. Grid: 2048 CTAs x 256 threads; each CTA owns
// MT=32 rows. Activations u(32x512) and z(32x512) stay in shared memory for
// the whole network; the 9 (512x512) weight matrices stream through a
// double-buffered 2x16KB smem slab (interleaved float4 copy: conflict-free
// STS.128). Each thread computes an 8x8 output tile (4 column PAIRS at float
// offsets 2q+128j, q=tid&63 -> conflict-free LDS.64) held in 32 packed f32x2
// accumulators -> FMA-pipe bound at the FFMA2 roofline.

#define H   512
#define MT  32
#define KS  8
#define NSLAB 64            // H / KS
#define NT  256

// shared memory layout (floats)
#define SM_U   0
#define SM_Z   (MT * H)              // 16384
#define SM_W   (2 * MT * H)          // 32768
#define SM_C   (SM_W + 2 * KS * H)   // 40960  (coords tile, 128)
#define SM_Y   (SM_C + 4 * MT)       // 41088  (y, 32)
#define SM_YS  (SM_Y + MT)           // 41120  (y*scale, 32)
#define SM_R1  (SM_YS + MT)          // 41152  (reduction scratch, 256)
#define SMEM_FLOATS (SM_R1 + NT)     // 41408
#define SMEM_BYTES  (SMEM_FLOATS * 4)

typedef unsigned long long ull;

__device__ __forceinline__ ull pk2(float lo, float hi) {
    ull d; asm("mov.b64 %0, {%1, %2};" : "=l"(d) : "f"(lo), "f"(hi)); return d;
}
__device__ __forceinline__ void up2(ull v, float& lo, float& hi) {
    asm("mov.b64 {%0, %1}, %2;" : "=f"(lo), "=f"(hi) : "l"(v));
}
__device__ __forceinline__ ull ffma2(ull a, ull b, ull c) {
    ull d; asm("fma.rn.f32x2 %0, %1, %2, %3;" : "=l"(d) : "l"(a), "l"(b), "l"(c));
    return d;
}

// acc[i][j] (+)= rows m0+i of aS[32xH] times W[HxH] column pair (2q+128j).
// Wg streamed global->smem double-buffered, KS=8 k-rows per slab.
__device__ __forceinline__ void gemm_tile(const float* __restrict__ Wg,
                                          const float* __restrict__ aS,
                                          float* __restrict__ wS,
                                          ull acc[8][4],
                                          int tid, int m0, int q, bool zero)
{
    if (zero) {
        #pragma unroll
        for (int i = 0; i < 8; i++)
            #pragma unroll
            for (int j = 0; j < 4; j++) acc[i][j] = 0ULL;
    }

    float4 pf0, pf1, pf2, pf3;
    {   // prime slab 0 (interleaved: lane-consecutive float4 -> coalesced STS.128)
        const float4* g = (const float4*)Wg;
        pf0 = g[tid]; pf1 = g[tid + NT]; pf2 = g[tid + 2 * NT]; pf3 = g[tid + 3 * NT];
        float4* d = (float4*)wS;
        d[tid] = pf0; d[tid + NT] = pf1; d[tid + 2 * NT] = pf2; d[tid + 3 * NT] = pf3;
    }
    __syncthreads();

    #pragma unroll 1
    for (int s = 0; s < NSLAB; s++) {
        if (s + 1 < NSLAB) {   // prefetch next slab into registers
            const float4* g = (const float4*)(Wg + (s + 1) * (KS * H));
            pf0 = g[tid]; pf1 = g[tid + NT]; pf2 = g[tid + 2 * NT]; pf3 = g[tid + 3 * NT];
        }
        const float* w = wS + (s & 1) * (KS * H);
        const float* a = aS + m0 * H + s * KS;

        #pragma unroll
        for (int kk = 0; kk < KS; kk += 4) {
            float4 av[8];
            #pragma unroll
            for (int i = 0; i < 8; i++)
                av[i] = *(const float4*)(a + i * H + kk);   // uniform addr: broadcast
            #pragma unroll
            for (int q4 = 0; q4 < 4; q4++) {
                // column pairs at float offset 2q + 128j: conflict-free LDS.64
                const ull* wp = (const ull*)(w + (kk + q4) * H + 2 * q);
                ull b0 = wp[0], b1 = wp[64], b2 = wp[128], b3 = wp[192];
                #pragma unroll
                for (int i = 0; i < 8; i++) {
                    float as = (q4 == 0) ? av[i].x : (q4 == 1) ? av[i].y
                             : (q4 == 2) ? av[i].z : av[i].w;
                    ull aa = pk2(as, as);
                    acc[i][0] = ffma2(aa, b0, acc[i][0]);
                    acc[i][1] = ffma2(aa, b1, acc[i][1]);
                    acc[i][2] = ffma2(aa, b2, acc[i][2]);
                    acc[i][3] = ffma2(aa, b3, acc[i][3]);
                }
            }
        }
        if (s + 1 < NSLAB) {
            float4* d = (float4*)(wS + ((s + 1) & 1) * (KS * H));
            d[tid] = pf0; d[tid + NT] = pf1; d[tid + 2 * NT] = pf2; d[tid + 3 * NT] = pf3;
        }
        __syncthreads();
    }
}

// ysS[m] = yS[m] * (dot(uS[m,:], wy) + byv)   (per-row H->1 reduction)
__device__ __forceinline__ void row_dot_ys(const float* __restrict__ uS,
                                           const float* __restrict__ wy,
                                           float byv,
                                           const float* __restrict__ yS,
                                           float* __restrict__ ysS,
                                           float* __restrict__ r1, int tid)
{
    int mm = tid >> 3, pt = tid & 7;
    const float* ur = uS + mm * H;
    float ps = 0.0f;
    #pragma unroll 8
    for (int t = 0; t < 64; t++) {
        int k = pt + (t << 3);
        ps += ur[k] * wy[k];
    }
    r1[tid] = ps;
    __syncthreads();
    if (tid < MT) {
        float s = byv;
        #pragma unroll
        for (int pp = 0; pp < 8; pp++) s += r1[tid * 8 + pp];
        ysS[tid] = yS[tid] * s;
    }
    __syncthreads();
}

__global__ void __launch_bounds__(NT, 1)
fcblock_kernel(const float* __restrict__ coords,
               const float* __restrict__ Wu0,   const float* __restrict__ bu0,
               const float* __restrict__ Wu,    const float* __restrict__ bu,
               const float* __restrict__ Wzuu,  const float* __restrict__ bzuu,
               const float* __restrict__ Wzzu,  const float* __restrict__ Wzzu_last,
               const float* __restrict__ Wyuu0, const float* __restrict__ byuu0,
               const float* __restrict__ Wyuu,  const float* __restrict__ byuu,
               const float* __restrict__ Wzyu,  const float* __restrict__ Wzyu_last,
               const float* __restrict__ Wzu0,  const float* __restrict__ bzu0,
               const float* __restrict__ Wzu,   const float* __restrict__ bzu,
               const float* __restrict__ Wzu_last, const float* __restrict__ bzu_last,
               const float* __restrict__ pP, const float* __restrict__ puP,
               const float* __restrict__ pzuP,
               float* __restrict__ out)
{
    extern __shared__ float sm[];
    float* uS  = sm + SM_U;
    float* zS  = sm + SM_Z;
    float* wS  = sm + SM_W;
    float* cS  = sm + SM_C;
    float* yS  = sm + SM_Y;
    float* ysS = sm + SM_YS;
    float* r1  = sm + SM_R1;

    const int tid = threadIdx.x;
    const int q   = tid & 63;          // column-pair owner, pairs 2q+128j
    const int m0  = (tid >> 6) * 8;    // first owned row
    const int R   = blockIdx.x * MT;

    const float cp   = 10.0f * pP[0];
    const float cpu  = 10.0f * puP[0];
    const float cpzu = 10.0f * pzuP[0];

    if (tid < 4 * MT) cS[tid] = coords[R * 4 + tid];
    __syncthreads();
    if (tid < MT) {
        float yv = cS[tid * 4 + 3];
        yS[tid] = yv;
        float s0 = cS[tid * 4 + 0] * Wyuu0[0] + cS[tid * 4 + 1] * Wyuu0[1]
                 + cS[tid * 4 + 2] * Wyuu0[2] + byuu0[0];
        ysS[tid] = yv * s0;
    }
    __syncthreads();

    // ---- init layer (K = 3): u0, z0 ----
    #pragma unroll
    for (int j = 0; j < 4; j++) {
        int n = 2 * q + 128 * j;
        #pragma unroll
        for (int e = 0; e < 2; e++) {
            int nn = n + e;
            float wu_0 = Wu0[nn],  wu_1 = Wu0[H + nn],  wu_2 = Wu0[2 * H + nn];
            float wz_0 = Wzu0[nn], wz_1 = Wzu0[H + nn], wz_2 = Wzu0[2 * H + nn];
            float bun = bu0[nn], bzn = bzu0[nn], wzyn = Wzyu[nn];   // Wzyu[0]
            #pragma unroll
            for (int i = 0; i < 8; i++) {
                int m = m0 + i;
                float c0 = cS[m * 4], c1 = cS[m * 4 + 1], c2 = cS[m * 4 + 2];
                uS[m * H + nn] = fmaxf(cpu * (c0 * wu_0 + c1 * wu_1 + c2 * wu_2 + bun), 0.0f);
                zS[m * H + nn] = fmaxf(cp  * (c0 * wz_0 + c1 * wz_1 + c2 * wz_2 + bzn
                                              + ysS[m] * wzyn), 0.0f);
            }
        }
    }
    // gemm_tile's prime-sync orders these writes before the first slab reads.

    ull acc[8][4];

    // ---- layers i = 1, 2 (jw = 0, 1) ----
    #pragma unroll 1
    for (int jw = 0; jw < 2; jw++) {
        // A: acc = u @ Wzuu[jw]
        gemm_tile(Wzuu + jw * H * H, uS, wS, acc, tid, m0, q, true);
        row_dot_ys(uS, Wyuu + jw * H, byuu[jw], yS, ysS, r1, tid);

        // zz = z * relu(cpzu*(acc + bzuu[jw]))  (in-place, own elements only)
        #pragma unroll
        for (int j = 0; j < 4; j++) {
            int n = 2 * q + 128 * j;
            float bz0 = bzuu[jw * H + n], bz1 = bzuu[jw * H + n + 1];
            #pragma unroll
            for (int i = 0; i < 8; i++) {
                float lo, hi; up2(acc[i][j], lo, hi);
                ull* zr = (ull*)(zS + (m0 + i) * H + n);
                float za, zb; up2(*zr, za, zb);
                za *= fmaxf(cpzu * (lo + bz0), 0.0f);
                zb *= fmaxf(cpzu * (hi + bz1), 0.0f);
                *zr = pk2(za, zb);
            }
        }

        // B: acc = zz @ Wzzu[jw] + u @ Wzu[jw]
        gemm_tile(Wzzu + jw * H * H, zS, wS, acc, tid, m0, q, true);
        gemm_tile(Wzu  + jw * H * H, uS, wS, acc, tid, m0, q, false);

        // z = relu(cp*(acc + bzu[jw] + ys * Wzyu[jw+1]))
        #pragma unroll
        for (int j = 0; j < 4; j++) {
            int n = 2 * q + 128 * j;
            float b0 = bzu[jw * H + n], b1 = bzu[jw * H + n + 1];
            float w0 = Wzyu[(jw + 1) * H + n], w1 = Wzyu[(jw + 1) * H + n + 1];
            #pragma unroll
            for (int i = 0; i < 8; i++) {
                float lo, hi; up2(acc[i][j], lo, hi);
                float ys = ysS[m0 + i];
                *(ull*)(zS + (m0 + i) * H + n) =
                    pk2(fmaxf(cp * (lo + b0 + ys * w0), 0.0f),
                        fmaxf(cp * (hi + b1 + ys * w1), 0.0f));
            }
        }

        // C: u = relu(cpu*(u @ Wu[jw] + bu[jw]))
        gemm_tile(Wu + jw * H * H, uS, wS, acc, tid, m0, q, true);
        #pragma unroll
        for (int j = 0; j < 4; j++) {
            int n = 2 * q + 128 * j;
            float b0 = bu[jw * H + n], b1 = bu[jw * H + n + 1];
            #pragma unroll
            for (int i = 0; i < 8; i++) {
                float lo, hi; up2(acc[i][j], lo, hi);
                *(ull*)(uS + (m0 + i) * H + n) =
                    pk2(fmaxf(cpu * (lo + b0), 0.0f), fmaxf(cpu * (hi + b1), 0.0f));
            }
        }
        __syncthreads();
    }

    // ---- final layer i = 3 (jw = 2) ----
    gemm_tile(Wzuu + 2 * H * H, uS, wS, acc, tid, m0, q, true);
    row_dot_ys(uS, Wyuu + 2 * H, byuu[2], yS, ysS, r1, tid);

    #pragma unroll
    for (int j = 0; j < 4; j++) {
        int n = 2 * q + 128 * j;
        float bz0 = bzuu[2 * H + n], bz1 = bzuu[2 * H + n + 1];
        #pragma unroll
        for (int i = 0; i < 8; i++) {
            float lo, hi; up2(acc[i][j], lo, hi);
            ull* zr = (ull*)(zS + (m0 + i) * H + n);
            float za, zb; up2(*zr, za, zb);
            za *= fmaxf(cpzu * (lo + bz0), 0.0f);
            zb *= fmaxf(cpzu * (hi + bz1), 0.0f);
            *zr = pk2(za, zb);
        }
    }
    __syncthreads();

    // out = zz @ Wzzu_last + u @ Wzu_last + bzu_last + ys * Wzyu_last
    {
        int mm = tid >> 3, pt = tid & 7;
        const float* zr = zS + mm * H;
        const float* ur = uS + mm * H;
        float ps = 0.0f;
        #pragma unroll 8
        for (int t = 0; t < 64; t++) {
            int k = pt + (t << 3);
            ps += zr[k] * Wzzu_last[k] + ur[k] * Wzu_last[k];
        }
        r1[tid] = ps;
        __syncthreads();
        if (tid < MT) {
            float s = bzu_last[0];
            #pragma unroll
            for (int pp = 0; pp < 8; pp++) s += r1[tid * 8 + pp];
            s += ysS[tid] * Wzyu_last[0];
            out[R + tid] = s;
        }
    }
}

extern "C" void kernel_launch(void* const* d_in, const int* in_sizes, int n_in,
                              void* d_out, int out_size)
{
    const float* coords    = (const float*)d_in[0];
    const float* Wu0       = (const float*)d_in[1];
    const float* bu0       = (const float*)d_in[2];
    const float* Wu        = (const float*)d_in[3];
    const float* bu        = (const float*)d_in[4];
    const float* Wzuu      = (const float*)d_in[5];
    const float* bzuu      = (const float*)d_in[6];
    const float* Wzzu      = (const float*)d_in[7];
    const float* Wzzu_last = (const float*)d_in[8];
    const float* Wyuu0     = (const float*)d_in[9];
    const float* byuu0     = (const float*)d_in[10];
    const float* Wyuu      = (const float*)d_in[11];
    const float* byuu      = (const float*)d_in[12];
    const float* Wzyu      = (const float*)d_in[13];
    const float* Wzyu_last = (const float*)d_in[14];
    const float* Wzu0      = (const float*)d_in[15];
    const float* bzu0      = (const float*)d_in[16];
    const float* Wzu       = (const float*)d_in[17];
    const float* bzu       = (const float*)d_in[18];
    const float* Wzu_last  = (const float*)d_in[19];
    const float* bzu_last  = (const float*)d_in[20];
    const float* p         = (const float*)d_in[21];
    const float* pu        = (const float*)d_in[22];
    const float* pzu       = (const float*)d_in[23];

    cudaFuncSetAttribute(fcblock_kernel,
                         cudaFuncAttributeMaxDynamicSharedMemorySize, SMEM_BYTES);

    int rows = in_sizes[0] / 4;          // N = 65536
    int grid = rows / MT;                // 2048
    fcblock_kernel<<<grid, NT, SMEM_BYTES>>>(
        coords, Wu0, bu0, Wu, bu, Wzuu, bzuu, Wzzu, Wzzu_last,
        Wyuu0, byuu0, Wyuu, byuu, Wzyu, Wzyu_last,
        Wzu0, bzu0, Wzu, bzu, Wzu_last, bzu_last,
        p, pu, pzu, (float*)d_out);
}